// round 14
// baseline (speedup 1.0000x reference)
#include <cuda_runtime.h>
#include <cuda_bf16.h>
#include <cuda_fp16.h>
#include <cstdint>

#define NB 8
#define SEQ 2048
#define DIM 768
#define MTOT (NB*SEQ)                    // 16384
#define INV_SCALE 0.03608439182435161f   // 1/sqrt(768)

// ---- fp16 GEMM tiling: 128x128 CTA, 4 warps (2x2), 64x64 warp tiles ----
#define TM 128
#define TN 128
#define TKH 64
#define KTH (DIM/TKH)                    // 12
#define RSH 144
#define AH_BYTES (TM*RSH)                // 18432
#define STAGE_H (2*AH_BYTES)             // 36864
#define NSTAGE 3
#define PTR_BYTES ((TM+TN)*8)
#define SW_BYTES 512
#define SMEM_DYN (NSTAGE*STAGE_H + PTR_BYTES + SW_BYTES)

#define QS 8                             // colsum q-split
#define XC 32                            // cx chunks

#define ROUND_BLKS 12288                 // MTOT*DIM/4/256
#define TRANS_BLKS 1152                  // 24*24*2
#define PREP_TOTAL (ROUND_BLKS + TRANS_BLKS + NB)

// ---------------- static device scratch (allocation-free) ----------------
__device__ __half g_xh [(size_t)MTOT*DIM];           // x fp16
__device__ __half g_Kp [(size_t)MTOT*DIM];           // K' = x_c * A^T, fp16 (compacted rows)
__device__ __half g_WqT[DIM*DIM];                    // Wq^T fp16 [d][o]
__device__ __half g_WkT[DIM*DIM];                    // Wk^T fp16 [d][o]
__device__ float  g_Apart[4][DIM*DIM];               // gemmA K-split partials (f32)
__device__ __half g_A  [DIM*DIM];                    // A[d][d'] = Wq^T Wk / sqrt(d), fp16
__device__ float  g_v  [DIM];                        // v = bq*Wk/sqrt(d)
__device__ float  g_w  [NB*SEQ];                     // w[b][k] = v . x_c[k]
__device__ __nv_bfloat16 g_P[(size_t)NB*SEQ*SEQ];    // P[q][kcol]
__device__ float g_Zpart[(size_t)MTOT*16];
__device__ float g_cpart[NB*QS*SEQ];
__device__ float g_ypart[NB*XC*DIM];
__device__ int   g_idx[NB*SEQ];
__device__ int   g_cnt[NB];

// ---------------- helpers ----------------
__device__ __forceinline__ uint32_t smem_u32(const void* p){
    uint32_t a;
    asm("{ .reg .u64 t; cvta.to.shared.u64 t, %1; cvt.u32.u64 %0, t; }" : "=r"(a) : "l"(p));
    return a;
}
__device__ __forceinline__ void cp16(uint32_t d, const void* s){
    asm volatile("cp.async.cg.shared.global [%0], [%1], 16;\n" :: "r"(d), "l"(s));
}
__device__ __forceinline__ void cp_commit(){ asm volatile("cp.async.commit_group;\n" ::); }
template<int N> __device__ __forceinline__ void cp_wait(){
    asm volatile("cp.async.wait_group %0;\n" :: "n"(N));
}
__device__ __forceinline__ void ldsm4(uint32_t addr, uint32_t* r){
    asm volatile("ldmatrix.sync.aligned.m8n8.x4.shared.b16 {%0,%1,%2,%3}, [%4];\n"
        : "=r"(r[0]), "=r"(r[1]), "=r"(r[2]), "=r"(r[3]) : "r"(addr));
}
__device__ __forceinline__ void mma_f16(float* c, const uint32_t* a, uint32_t b0, uint32_t b1){
    asm volatile("mma.sync.aligned.m16n8k16.row.col.f32.f16.f16.f32 "
        "{%0,%1,%2,%3},{%4,%5,%6,%7},{%8,%9},{%0,%1,%2,%3};\n"
        : "+f"(c[0]), "+f"(c[1]), "+f"(c[2]), "+f"(c[3])
        : "r"(a[0]), "r"(a[1]), "r"(a[2]), "r"(a[3]), "r"(b0), "r"(b1));
}
__device__ __forceinline__ float bf16lo(uint32_t v){ return __uint_as_float(v << 16); }
__device__ __forceinline__ float bf16hi(uint32_t v){ return __uint_as_float(v & 0xffff0000u); }

// ================= fp16-input / f32-acc GEMM core =================
__device__ __forceinline__ void issue_stage_h(uint32_t sb, int s, int k0,
        const __half* const* rowA, const __half* const* rowB, int t){
    uint32_t base = sb + s*STAGE_H;
#pragma unroll
    for (int j=0;j<8;j++){
        int ci = t + j*128; int r = ci>>3, c = ci&7;
        cp16(base + r*RSH + c*16, rowA[r] + k0 + c*8);
    }
    uint32_t bb = base + AH_BYTES;
#pragma unroll
    for (int j=0;j<8;j++){
        int ci = t + j*128; int r = ci>>3, c = ci&7;
        cp16(bb + r*RSH + c*16, rowB[r] + k0 + c*8);
    }
    cp_commit();
}

__device__ __forceinline__ void compute_stage(uint32_t sb, int s, int wm, int wn,
        uint32_t laneA, uint32_t laneB, float acc[4][8][4]){
    uint32_t aT = sb + s*STAGE_H + wm*64*RSH + laneA;
    uint32_t bT = sb + s*STAGE_H + AH_BYTES + wn*64*RSH + laneB;
#pragma unroll
    for (int kk=0; kk<4; kk++){
        uint32_t a[4][4], bb[4][4];
#pragma unroll
        for (int mf=0;mf<4;mf++) ldsm4(aT + mf*16*RSH + kk*32, a[mf]);
#pragma unroll
        for (int nf=0;nf<4;nf++) ldsm4(bT + nf*16*RSH + kk*32, bb[nf]);
#pragma unroll
        for (int mf=0;mf<4;mf++)
#pragma unroll
            for (int nf=0;nf<4;nf++){
                mma_f16(acc[mf][2*nf],   a[mf], bb[nf][0], bb[nf][1]);
                mma_f16(acc[mf][2*nf+1], a[mf], bb[nf][2], bb[nf][3]);
            }
    }
}

__device__ __forceinline__ void gemm_main(uint32_t sb, const __half* const* rowA,
        const __half* const* rowB, int t, int wm, int wn,
        uint32_t laneA, uint32_t laneB, float acc[4][8][4], int kiters){
    issue_stage_h(sb, 0, 0,   rowA, rowB, t);
    issue_stage_h(sb, 1, TKH, rowA, rowB, t);
#pragma unroll 1
    for (int it=0; it<kiters; ++it){
        if (it < kiters-1) cp_wait<1>(); else cp_wait<0>();
        __syncthreads();
        if (it+2 < kiters) issue_stage_h(sb, (it+2)%NSTAGE, (it+2)*TKH, rowA, rowB, t);
        compute_stage(sb, it%NSTAGE, wm, wn, laneA, laneB, acc);
    }
}

// ---------------- kernel 1: fused prep (x->fp16, W transposes, mask scan) ------------
__global__ void prep_all(const float* __restrict__ x,
                         const float* __restrict__ Wq, const float* __restrict__ Wk,
                         const int* __restrict__ mask){
    int bid = blockIdx.x;
    int t = threadIdx.x;
    if (bid < ROUND_BLKS){
        size_t i = ((size_t)bid*256 + t)*4;
        float4 v = *(const float4*)(x+i);
        *(__half2*)(g_xh+i)   = __floats2half2_rn(v.x, v.y);
        *(__half2*)(g_xh+i+2) = __floats2half2_rn(v.z, v.w);
        return;
    }
    if (bid < ROUND_BLKS + TRANS_BLKS){
        __shared__ float tile[32][33];
        int r = bid - ROUND_BLKS;
        int z = r / 576; r %= 576;
        int bx = r % 24, by = r / 24;
        const float* src = z ? Wk : Wq;
        __half* dst = z ? g_WkT : g_WqT;
        int o0 = bx*32, d0 = by*32;
        int tx = t & 31, ty = t >> 5;
#pragma unroll
        for (int i=0;i<32;i+=8)
            tile[ty+i][tx] = src[(size_t)(o0+ty+i)*DIM + d0+tx];
        __syncthreads();
#pragma unroll
        for (int i=0;i<32;i+=8)
            dst[(size_t)(d0+ty+i)*DIM + o0+tx] = __float2half(tile[tx][ty+i]);
        return;
    }
    // mask prefix-scan
    {
        __shared__ int sm[SEQ];
        __shared__ int ws[8];
        int b = bid - ROUND_BLKS - TRANS_BLKS;
        for (int i=t;i<SEQ;i+=256) sm[i] = mask[b*SEQ+i];
        __syncthreads();
        int base_i = t*8;
        int loc[8], s=0;
#pragma unroll
        for (int j=0;j<8;j++){ loc[j]=s; s += sm[base_i+j]; }
        int lane = t&31, w = t>>5;
        int v = s;
#pragma unroll
        for (int off=1; off<32; off<<=1){
            int n = __shfl_up_sync(0xffffffffu, v, off);
            if (lane >= off) v += n;
        }
        if (lane==31) ws[w] = v;
        __syncthreads();
        int wbase = 0;
#pragma unroll
        for (int i=0;i<8;i++) if (i<w) wbase += ws[i];
        int excl = wbase + v - s;
#pragma unroll
        for (int j=0;j<8;j++)
            if (sm[base_i+j]) g_idx[b*SEQ + excl + loc[j]] = base_i+j;
        if (t==255) g_cnt[b] = wbase + v;
    }
}

// ---------------- kernel 2: A partials (K-split x4) ----------------
__global__ void __launch_bounds__(128,2) gemmA_k(){
    extern __shared__ __align__(16) char dsm[];
    uint32_t sb = smem_u32(dsm);
    const __half** rowA = (const __half**)(dsm + NSTAGE*STAGE_H);
    const __half** rowB = rowA + TM;
    int t = threadIdx.x, L = t&31, w = t>>5;
    int wm = w&1, wn = w>>1;
    int mBase = blockIdx.y*TM, nBase = blockIdx.x*TN;
    int z = blockIdx.z;
    rowA[t] = g_WqT + (size_t)(mBase + t)*DIM + z*192;
    rowB[t] = g_WkT + (size_t)(nBase + t)*DIM + z*192;
    __syncthreads();
    uint32_t laneA = (L&15)*RSH + ((L>>4)&1)*16;
    uint32_t laneB = ((L&7) + ((L>>4)&1)*8)*RSH + ((L>>3)&1)*16;
    float acc[4][8][4] = {};
    gemm_main(sb, rowA, rowB, t, wm, wn, laneA, laneB, acc, 3);
    int gq = L>>2, tig = L&3;
    float* Ap = g_Apart[z];
#pragma unroll
    for (int mf=0;mf<4;mf++){
        int r0 = mBase + wm*64 + mf*16 + gq;
#pragma unroll
        for (int j=0;j<8;j++){
            int col = nBase + wn*64 + (j>>1)*16 + (j&1)*8 + tig*2;
            *(float2*)&Ap[(size_t)r0*DIM + col]     = make_float2(acc[mf][j][0], acc[mf][j][1]);
            *(float2*)&Ap[(size_t)(r0+8)*DIM + col] = make_float2(acc[mf][j][2], acc[mf][j][3]);
        }
    }
}

// ---------------- kernel 3: fused A-reduce + v calc ----------------
__global__ void areduce_v(const float* __restrict__ bq){
    int bid = blockIdx.x;
    int t = threadIdx.x;
    if (bid < 576){
        size_t i = ((size_t)bid*256 + t)*4;
        float4 p0 = *(const float4*)&g_Apart[0][i];
        float4 p1 = *(const float4*)&g_Apart[1][i];
        float4 p2 = *(const float4*)&g_Apart[2][i];
        float4 p3 = *(const float4*)&g_Apart[3][i];
        float a0 = (p0.x+p1.x+p2.x+p3.x)*INV_SCALE;
        float a1 = (p0.y+p1.y+p2.y+p3.y)*INV_SCALE;
        float a2 = (p0.z+p1.z+p2.z+p3.z)*INV_SCALE;
        float a3 = (p0.w+p1.w+p2.w+p3.w)*INV_SCALE;
        *(__half2*)(g_A+i)   = __floats2half2_rn(a0,a1);
        *(__half2*)(g_A+i+2) = __floats2half2_rn(a2,a3);
        return;
    }
    // v[d] = sum_o bq[o]*WkT[d][o]*INV_SCALE
    int gw = ((bid-576)*256 + t) >> 5;
    int lane = t & 31;
    if (gw >= DIM) return;
    const __half* row = g_WkT + (size_t)gw*DIM;
    float s = 0.f;
#pragma unroll 4
    for (int o=lane; o<DIM; o+=32) s += bq[o]*__half2float(row[o]);
#pragma unroll
    for (int off=16; off; off>>=1) s += __shfl_xor_sync(0xffffffffu, s, off);
    if (lane==0) g_v[gw] = s*INV_SCALE;
}

// ---------------- kernel 4: K' = x_c * A^T (+ fused w calc on x==0) ----------------
__global__ void __launch_bounds__(128,2) kproj_k(){
    int y = blockIdx.y;
    int b = y >> 4;
    int mBase = (y & 15)*TM;
    int cnt = g_cnt[b];
    int cntp = ((cnt + 127) >> 7) << 7;
    if (mBase >= cntp) return;
    extern __shared__ __align__(16) char dsm[];
    uint32_t sb = smem_u32(dsm);
    const __half** rowA = (const __half**)(dsm + NSTAGE*STAGE_H);
    const __half** rowB = rowA + TM;
    int t = threadIdx.x, L = t&31, w = t>>5;
    int wm = w&1, wn = w>>1;
    int nBase = blockIdx.x*TN;
    {
        int j = mBase + t; if (j >= cnt) j = cnt-1;
        rowA[t] = g_xh + ((size_t)b*SEQ + g_idx[b*SEQ + j])*DIM;
    }
    rowB[t] = g_A + (size_t)(nBase + t)*DIM;
    __syncthreads();
    uint32_t laneA = (L&15)*RSH + ((L>>4)&1)*16;
    uint32_t laneB = ((L&7) + ((L>>4)&1)*8)*RSH + ((L>>3)&1)*16;
    float acc[4][8][4] = {};
    gemm_main(sb, rowA, rowB, t, wm, wn, laneA, laneB, acc, KTH);
    int gq = L>>2, tig = L&3;
    __half* out = g_Kp + (size_t)b*SEQ*DIM;
#pragma unroll
    for (int mf=0;mf<4;mf++){
        int r0 = mBase + wm*64 + mf*16 + gq;
#pragma unroll
        for (int j=0;j<8;j++){
            int col = nBase + wn*64 + (j>>1)*16 + (j&1)*8 + tig*2;
            *(__half2*)&out[(size_t)r0*DIM + col]     = __floats2half2_rn(acc[mf][j][0], acc[mf][j][1]);
            *(__half2*)&out[(size_t)(r0+8)*DIM + col] = __floats2half2_rn(acc[mf][j][2], acc[mf][j][3]);
        }
    }
    // fused wcalc: thread t computes w[b][mBase+t] = v . x_c[mBase+t]
    if (blockIdx.x == 0){
        const __half2* xr = (const __half2*)rowA[t];
        float s = 0.f;
#pragma unroll 4
        for (int i=0;i<DIM/2;i++){
            float2 f = __half22float2(xr[i]);
            s += g_v[2*i]*f.x + g_v[2*i+1]*f.y;
        }
        g_w[b*SEQ + mBase + t] = s;
    }
}

// ---------------- kernel 5: scores = x*K'^T + w, P=exp, Z partials ----------------
__global__ void __launch_bounds__(128,2) scores_k(){
    int b = blockIdx.z;
    int cnt = g_cnt[b];
    int cntp = ((cnt + 127) >> 7) << 7;
    int nBase = blockIdx.x*TN;
    if (nBase >= cntp) return;
    int mBase = blockIdx.y*TM;
    extern __shared__ __align__(16) char dsm[];
    uint32_t sb = smem_u32(dsm);
    const __half** rowA = (const __half**)(dsm + NSTAGE*STAGE_H);
    const __half** rowB = rowA + TM;
    float* sW = (float*)(dsm + NSTAGE*STAGE_H + PTR_BYTES);
    float* sRow = (float*)dsm;                  // reused after mainloop
    int t = threadIdx.x, L = t&31, w = t>>5;
    int wm = w&1, wn = w>>1;
    rowA[t] = g_xh + ((size_t)b*SEQ + mBase + t)*DIM;
    {
        int j = nBase + t; if (j >= cnt) j = cnt-1;
        rowB[t] = g_Kp + ((size_t)b*SEQ + j)*DIM;
    }
    sW[t] = g_w[b*SEQ + nBase + t];
    __syncthreads();
    uint32_t laneA = (L&15)*RSH + ((L>>4)&1)*16;
    uint32_t laneB = ((L&7) + ((L>>4)&1)*8)*RSH + ((L>>3)&1)*16;
    float acc[4][8][4] = {};
    gemm_main(sb, rowA, rowB, t, wm, wn, laneA, laneB, acc, KTH);

    int gq = L>>2, tig = L&3;
    __nv_bfloat16* P = g_P + (size_t)b*SEQ*SEQ;
    float zl[4] = {0,0,0,0}, zh[4] = {0,0,0,0};
#pragma unroll
    for (int mf=0;mf<4;mf++){
        int q0 = mBase + wm*64 + mf*16 + gq;
#pragma unroll
        for (int j=0;j<8;j++){
            int coll = wn*64 + (j>>1)*16 + (j&1)*8 + tig*2;
            int kcol = nBase + coll;
            float w0 = sW[coll], w1 = sW[coll+1];
            float p0 = (kcol   < cnt) ? __expf(acc[mf][j][0]+w0) : 0.f;
            float p1 = (kcol+1 < cnt) ? __expf(acc[mf][j][1]+w1) : 0.f;
            float p2 = (kcol   < cnt) ? __expf(acc[mf][j][2]+w0) : 0.f;
            float p3 = (kcol+1 < cnt) ? __expf(acc[mf][j][3]+w1) : 0.f;
            *(__nv_bfloat162*)&P[(size_t)q0*SEQ + kcol]     = __floats2bfloat162_rn(p0,p1);
            *(__nv_bfloat162*)&P[(size_t)(q0+8)*SEQ + kcol] = __floats2bfloat162_rn(p2,p3);
            zl[mf] += p0+p1; zh[mf] += p2+p3;
        }
    }
    __syncthreads();
#pragma unroll
    for (int mf=0;mf<4;mf++){
        float x0 = zl[mf];
        x0 += __shfl_xor_sync(0xffffffffu, x0, 1);
        x0 += __shfl_xor_sync(0xffffffffu, x0, 2);
        float x1 = zh[mf];
        x1 += __shfl_xor_sync(0xffffffffu, x1, 1);
        x1 += __shfl_xor_sync(0xffffffffu, x1, 2);
        if (tig==0){
            sRow[(wm*64 + mf*16 + gq)*2     + wn] = x0;
            sRow[(wm*64 + mf*16 + gq + 8)*2 + wn] = x1;
        }
    }
    __syncthreads();
    if (t < TM){
        float z = sRow[t*2] + sRow[t*2+1];
        g_Zpart[((size_t)b*SEQ + mBase + t)*16 + blockIdx.x] = z;
    }
}

// ---------------- kernel 6: colsum with inline Z-reduce ----------------
__global__ void __launch_bounds__(256) colsum_k(){
    int b = blockIdx.y, qc = blockIdx.z;
    int cnt = g_cnt[b];
    int cntp = ((cnt + 127) >> 7) << 7;
    int t = threadIdx.x;
    int k0 = (blockIdx.x*256 + t)*2;
    float* dst = g_cpart + ((size_t)(b*QS + qc))*SEQ;
    if (blockIdx.x*512 >= cntp){ dst[k0] = 0.f; dst[k0+1] = 0.f; return; }
    __shared__ float sz[SEQ/QS];
    int qBase = qc*(SEQ/QS);
    {
        int nt = (cnt + 127) >> 7;
        float s = 0.f;
        const float* zp = &g_Zpart[((size_t)b*SEQ + qBase + t)*16];
        for (int j=0;j<nt;j++) s += zp[j];
        sz[t] = 1.0f/s;
    }
    __syncthreads();
    const uint32_t* P2 = (const uint32_t*)(g_P + (size_t)b*SEQ*SEQ + (size_t)qBase*SEQ)
                         + (blockIdx.x*256 + t);
    float c0=0.f, c1=0.f, d0=0.f, d1=0.f;
#pragma unroll 4
    for (int q=0; q<SEQ/QS; q+=2){
        uint32_t v0 = P2[(size_t)q*(SEQ/2)];
        uint32_t v1 = P2[(size_t)(q+1)*(SEQ/2)];
        c0 += bf16lo(v0)*sz[q];   c1 += bf16hi(v0)*sz[q];
        d0 += bf16lo(v1)*sz[q+1]; d1 += bf16hi(v1)*sz[q+1];
    }
    dst[k0] = c0+d0; dst[k0+1] = c1+d1;
}

// ---------------- kernel 7: ypart = c-chunk @ X_c ----------------
__global__ void __launch_bounds__(384) cx_k(){
    int b = blockIdx.y;
    int kc = blockIdx.x*64;
    int t = threadIdx.x;
    int cnt = g_cnt[b];
    float* yp = g_ypart + ((size_t)(b*XC + blockIdx.x))*DIM;
    if (kc >= cnt){ yp[2*t] = 0.f; yp[2*t+1] = 0.f; return; }
    __shared__ float sc[64];
    __shared__ int  sidx[64];
    if (t < 64){
        float s = 0.f;
#pragma unroll
        for (int qc=0;qc<QS;qc++)
            s += g_cpart[((size_t)(b*QS+qc))*SEQ + kc + t];
        sc[t] = (kc + t < cnt) ? s : 0.f;
        int j = kc + t; if (j >= cnt) j = cnt-1;
        sidx[t] = g_idx[b*SEQ + j];
    }
    __syncthreads();
    float a0=0.f, a1=0.f;
#pragma unroll 1
    for (int r=0;r<64;r+=4){
#pragma unroll
        for (int u=0;u<4;u++){
            float cv = sc[r+u];
            const __half2* xr = (const __half2*)(g_xh + ((size_t)b*SEQ + sidx[r+u])*DIM);
            float2 f = __half22float2(xr[t]);
            a0 += cv*f.x; a1 += cv*f.y;
        }
    }
    yp[2*t] = a0; yp[2*t+1] = a1;
}

// ---------------- kernel 8: out = (1/S)*y*Wv^T + bv ----------------
__global__ void __launch_bounds__(256) wv_k(const float* __restrict__ Wv,
        const float* __restrict__ bv, float* __restrict__ out){
    int b = blockIdx.y, t = threadIdx.x;
    __shared__ float sy[DIM];
    for (int d=t; d<DIM; d+=256){
        float s = 0.f;
#pragma unroll
        for (int ch=0; ch<XC; ch++) s += g_ypart[((size_t)(b*XC+ch))*DIM + d];
        sy[d] = s;
    }
    __syncthreads();
    int o = blockIdx.x*256 + t;
    const float* wr = Wv + (size_t)o*DIM;
    float acc = 0.f;
#pragma unroll 4
    for (int d=0; d<DIM; d+=4){
        float4 w4 = *(const float4*)(wr + d);
        acc += w4.x*sy[d] + w4.y*sy[d+1] + w4.z*sy[d+2] + w4.w*sy[d+3];
    }
    out[b*DIM + o] = acc * (1.0f/(float)SEQ) + bv[o];
}

// ---------------- launch ----------------
extern "C" void kernel_launch(void* const* d_in, const int* in_sizes, int n_in,
                              void* d_out, int out_size){
    const float* x    = (const float*)d_in[0];
    const int*   mask = (const int*)  d_in[1];
    const float* Wq   = (const float*)d_in[2];
    const float* bq   = (const float*)d_in[3];
    const float* Wk   = (const float*)d_in[4];
    const float* bk   = (const float*)d_in[5];
    const float* Wv   = (const float*)d_in[6];
    const float* bv   = (const float*)d_in[7];
    (void)bk;
    float* out = (float*)d_out;

    cudaFuncSetAttribute(gemmA_k,  cudaFuncAttributeMaxDynamicSharedMemorySize, SMEM_DYN);
    cudaFuncSetAttribute(kproj_k,  cudaFuncAttributeMaxDynamicSharedMemorySize, SMEM_DYN);
    cudaFuncSetAttribute(scores_k, cudaFuncAttributeMaxDynamicSharedMemorySize, SMEM_DYN);

    prep_all  <<<PREP_TOTAL, 256>>>(x, Wq, Wk, mask);
    gemmA_k   <<<dim3(6,6,4), 128, SMEM_DYN>>>();
    areduce_v <<<672, 256>>>(bq);
    kproj_k   <<<dim3(6,128), 128, SMEM_DYN>>>();
    scores_k  <<<dim3(16,16,8), 128, SMEM_DYN>>>();
    colsum_k  <<<dim3(4,NB,QS), 256>>>();
    cx_k      <<<dim3(XC,NB), 384>>>();
    wv_k      <<<dim3(3,NB), 256>>>(Wv, bv, out);
}

// round 16
// speedup vs baseline: 1.1945x; 1.1945x over previous
#include <cuda_runtime.h>
#include <cuda_bf16.h>
#include <cuda_fp16.h>
#include <cstdint>

#define NB 8
#define SEQ 2048
#define DIM 768
#define MTOT (NB*SEQ)                    // 16384
#define INV_SCALE 0.03608439182435161f   // 1/sqrt(768)

// ---- fp16 GEMM tiling: 128x128 CTA, 4 warps (2x2), 64x64 warp tiles ----
#define TM 128
#define TN 128
#define TKH 64
#define KTH (DIM/TKH)                    // 12
#define RSH 144
#define AH_BYTES (TM*RSH)                // 18432
#define STAGE_H (2*AH_BYTES)             // 36864
#define NSTAGE 3
#define PTR_BYTES ((TM+TN)*8)
#define SW_BYTES 512
#define SMEM_DYN (NSTAGE*STAGE_H + PTR_BYTES + SW_BYTES)

#define QS 8                             // colsum q-split
#define XC 32                            // cx chunks

#define ROUND_BLKS 12288                 // MTOT*DIM/4/256
#define TRANS_BLKS 1152                  // 24*24*2
#define PREP_TOTAL (ROUND_BLKS + TRANS_BLKS + NB)

// ---------------- static device scratch (allocation-free) ----------------
__device__ __half g_xh [(size_t)MTOT*DIM];           // x fp16
__device__ __half g_Kp [(size_t)MTOT*DIM];           // K' = x_c * A^T, fp16 (compacted rows)
__device__ __half g_WqT[DIM*DIM];                    // Wq^T fp16 [d][o]
__device__ __half g_WkT[DIM*DIM];                    // Wk^T fp16 [d][o]
__device__ float  g_Apart[4][DIM*DIM];               // gemmA K-split partials (f32)
__device__ __half g_A  [DIM*DIM];                    // A[d][d'] = Wq^T Wk / sqrt(d), fp16
__device__ float  g_v  [DIM];                        // v = bq*Wk/sqrt(d)
__device__ float  g_w  [NB*SEQ];                     // w[b][k] = v . x_c[k]
__device__ __nv_bfloat16 g_P[(size_t)NB*SEQ*SEQ];    // P[q][kcol]
__device__ float g_Zpart[(size_t)MTOT*16];
__device__ float g_cpart[NB*QS*SEQ];
__device__ float g_ypart[NB*XC*DIM];
__device__ int   g_idx[NB*SEQ];
__device__ int   g_cnt[NB];

// ---------------- helpers ----------------
__device__ __forceinline__ uint32_t smem_u32(const void* p){
    uint32_t a;
    asm("{ .reg .u64 t; cvta.to.shared.u64 t, %1; cvt.u32.u64 %0, t; }" : "=r"(a) : "l"(p));
    return a;
}
__device__ __forceinline__ void cp16(uint32_t d, const void* s){
    asm volatile("cp.async.cg.shared.global [%0], [%1], 16;\n" :: "r"(d), "l"(s));
}
__device__ __forceinline__ void cp_commit(){ asm volatile("cp.async.commit_group;\n" ::); }
template<int N> __device__ __forceinline__ void cp_wait(){
    asm volatile("cp.async.wait_group %0;\n" :: "n"(N));
}
__device__ __forceinline__ void ldsm4(uint32_t addr, uint32_t* r){
    asm volatile("ldmatrix.sync.aligned.m8n8.x4.shared.b16 {%0,%1,%2,%3}, [%4];\n"
        : "=r"(r[0]), "=r"(r[1]), "=r"(r[2]), "=r"(r[3]) : "r"(addr));
}
__device__ __forceinline__ void mma_f16(float* c, const uint32_t* a, uint32_t b0, uint32_t b1){
    asm volatile("mma.sync.aligned.m16n8k16.row.col.f32.f16.f16.f32 "
        "{%0,%1,%2,%3},{%4,%5,%6,%7},{%8,%9},{%0,%1,%2,%3};\n"
        : "+f"(c[0]), "+f"(c[1]), "+f"(c[2]), "+f"(c[3])
        : "r"(a[0]), "r"(a[1]), "r"(a[2]), "r"(a[3]), "r"(b0), "r"(b1));
}
__device__ __forceinline__ float bf16lo(uint32_t v){ return __uint_as_float(v << 16); }
__device__ __forceinline__ float bf16hi(uint32_t v){ return __uint_as_float(v & 0xffff0000u); }

// ================= fp16-input / f32-acc GEMM core =================
__device__ __forceinline__ void issue_stage_h(uint32_t sb, int s, int k0,
        const __half* const* rowA, const __half* const* rowB, int t){
    uint32_t base = sb + s*STAGE_H;
#pragma unroll
    for (int j=0;j<8;j++){
        int ci = t + j*128; int r = ci>>3, c = ci&7;
        cp16(base + r*RSH + c*16, rowA[r] + k0 + c*8);
    }
    uint32_t bb = base + AH_BYTES;
#pragma unroll
    for (int j=0;j<8;j++){
        int ci = t + j*128; int r = ci>>3, c = ci&7;
        cp16(bb + r*RSH + c*16, rowB[r] + k0 + c*8);
    }
    cp_commit();
}

__device__ __forceinline__ void compute_stage(uint32_t sb, int s, int wm, int wn,
        uint32_t laneA, uint32_t laneB, float acc[4][8][4]){
    uint32_t aT = sb + s*STAGE_H + wm*64*RSH + laneA;
    uint32_t bT = sb + s*STAGE_H + AH_BYTES + wn*64*RSH + laneB;
#pragma unroll
    for (int kk=0; kk<4; kk++){
        uint32_t a[4][4], bb[4][4];
#pragma unroll
        for (int mf=0;mf<4;mf++) ldsm4(aT + mf*16*RSH + kk*32, a[mf]);
#pragma unroll
        for (int nf=0;nf<4;nf++) ldsm4(bT + nf*16*RSH + kk*32, bb[nf]);
#pragma unroll
        for (int mf=0;mf<4;mf++)
#pragma unroll
            for (int nf=0;nf<4;nf++){
                mma_f16(acc[mf][2*nf],   a[mf], bb[nf][0], bb[nf][1]);
                mma_f16(acc[mf][2*nf+1], a[mf], bb[nf][2], bb[nf][3]);
            }
    }
}

__device__ __forceinline__ void gemm_main(uint32_t sb, const __half* const* rowA,
        const __half* const* rowB, int t, int wm, int wn,
        uint32_t laneA, uint32_t laneB, float acc[4][8][4], int kiters){
    issue_stage_h(sb, 0, 0,   rowA, rowB, t);
    issue_stage_h(sb, 1, TKH, rowA, rowB, t);
#pragma unroll 1
    for (int it=0; it<kiters; ++it){
        if (it < kiters-1) cp_wait<1>(); else cp_wait<0>();
        __syncthreads();
        if (it+2 < kiters) issue_stage_h(sb, (it+2)%NSTAGE, (it+2)*TKH, rowA, rowB, t);
        compute_stage(sb, it%NSTAGE, wm, wn, laneA, laneB, acc);
    }
}

// ---------------- kernel 1: fused prep (x->fp16, W transposes, mask scan) ------------
__global__ void prep_all(const float* __restrict__ x,
                         const float* __restrict__ Wq, const float* __restrict__ Wk,
                         const int* __restrict__ mask){
    int bid = blockIdx.x;
    int t = threadIdx.x;
    if (bid < ROUND_BLKS){
        size_t i = ((size_t)bid*256 + t)*4;
        float4 v = *(const float4*)(x+i);
        *(__half2*)(g_xh+i)   = __floats2half2_rn(v.x, v.y);
        *(__half2*)(g_xh+i+2) = __floats2half2_rn(v.z, v.w);
        return;
    }
    if (bid < ROUND_BLKS + TRANS_BLKS){
        __shared__ float tile[32][33];
        int r = bid - ROUND_BLKS;
        int z = r / 576; r %= 576;
        int bx = r % 24, by = r / 24;
        const float* src = z ? Wk : Wq;
        __half* dst = z ? g_WkT : g_WqT;
        int o0 = bx*32, d0 = by*32;
        int tx = t & 31, ty = t >> 5;
#pragma unroll
        for (int i=0;i<32;i+=8)
            tile[ty+i][tx] = src[(size_t)(o0+ty+i)*DIM + d0+tx];
        __syncthreads();
#pragma unroll
        for (int i=0;i<32;i+=8)
            dst[(size_t)(d0+ty+i)*DIM + o0+tx] = __float2half(tile[tx][ty+i]);
        return;
    }
    // mask prefix-scan
    {
        __shared__ int sm[SEQ];
        __shared__ int ws[8];
        int b = bid - ROUND_BLKS - TRANS_BLKS;
        for (int i=t;i<SEQ;i+=256) sm[i] = mask[b*SEQ+i];
        __syncthreads();
        int base_i = t*8;
        int loc[8], s=0;
#pragma unroll
        for (int j=0;j<8;j++){ loc[j]=s; s += sm[base_i+j]; }
        int lane = t&31, w = t>>5;
        int v = s;
#pragma unroll
        for (int off=1; off<32; off<<=1){
            int n = __shfl_up_sync(0xffffffffu, v, off);
            if (lane >= off) v += n;
        }
        if (lane==31) ws[w] = v;
        __syncthreads();
        int wbase = 0;
#pragma unroll
        for (int i=0;i<8;i++) if (i<w) wbase += ws[i];
        int excl = wbase + v - s;
#pragma unroll
        for (int j=0;j<8;j++)
            if (sm[base_i+j]) g_idx[b*SEQ + excl + loc[j]] = base_i+j;
        if (t==255) g_cnt[b] = wbase + v;
    }
}

// ---------------- kernel 2: A partials (K-split x4) ----------------
__global__ void __launch_bounds__(128,2) gemmA_k(){
    extern __shared__ __align__(16) char dsm[];
    uint32_t sb = smem_u32(dsm);
    const __half** rowA = (const __half**)(dsm + NSTAGE*STAGE_H);
    const __half** rowB = rowA + TM;
    int t = threadIdx.x, L = t&31, w = t>>5;
    int wm = w&1, wn = w>>1;
    int mBase = blockIdx.y*TM, nBase = blockIdx.x*TN;
    int z = blockIdx.z;
    rowA[t] = g_WqT + (size_t)(mBase + t)*DIM + z*192;
    rowB[t] = g_WkT + (size_t)(nBase + t)*DIM + z*192;
    __syncthreads();
    uint32_t laneA = (L&15)*RSH + ((L>>4)&1)*16;
    uint32_t laneB = ((L&7) + ((L>>4)&1)*8)*RSH + ((L>>3)&1)*16;
    float acc[4][8][4] = {};
    gemm_main(sb, rowA, rowB, t, wm, wn, laneA, laneB, acc, 3);
    int gq = L>>2, tig = L&3;
    float* Ap = g_Apart[z];
#pragma unroll
    for (int mf=0;mf<4;mf++){
        int r0 = mBase + wm*64 + mf*16 + gq;
#pragma unroll
        for (int j=0;j<8;j++){
            int col = nBase + wn*64 + (j>>1)*16 + (j&1)*8 + tig*2;
            *(float2*)&Ap[(size_t)r0*DIM + col]     = make_float2(acc[mf][j][0], acc[mf][j][1]);
            *(float2*)&Ap[(size_t)(r0+8)*DIM + col] = make_float2(acc[mf][j][2], acc[mf][j][3]);
        }
    }
}

// ---------------- kernel 3: fused A-reduce + v calc ----------------
__global__ void areduce_v(const float* __restrict__ bq){
    int bid = blockIdx.x;
    int t = threadIdx.x;
    if (bid < 576){
        size_t i = ((size_t)bid*256 + t)*4;
        float4 p0 = *(const float4*)&g_Apart[0][i];
        float4 p1 = *(const float4*)&g_Apart[1][i];
        float4 p2 = *(const float4*)&g_Apart[2][i];
        float4 p3 = *(const float4*)&g_Apart[3][i];
        float a0 = (p0.x+p1.x+p2.x+p3.x)*INV_SCALE;
        float a1 = (p0.y+p1.y+p2.y+p3.y)*INV_SCALE;
        float a2 = (p0.z+p1.z+p2.z+p3.z)*INV_SCALE;
        float a3 = (p0.w+p1.w+p2.w+p3.w)*INV_SCALE;
        *(__half2*)(g_A+i)   = __floats2half2_rn(a0,a1);
        *(__half2*)(g_A+i+2) = __floats2half2_rn(a2,a3);
        return;
    }
    // v[d] = sum_o bq[o]*WkT[d][o]*INV_SCALE
    int gw = ((bid-576)*256 + t) >> 5;
    int lane = t & 31;
    if (gw >= DIM) return;
    const __half* row = g_WkT + (size_t)gw*DIM;
    float s = 0.f;
#pragma unroll 4
    for (int o=lane; o<DIM; o+=32) s += bq[o]*__half2float(row[o]);
#pragma unroll
    for (int off=16; off; off>>=1) s += __shfl_xor_sync(0xffffffffu, s, off);
    if (lane==0) g_v[gw] = s*INV_SCALE;
}

// ---------------- kernel 4: K' = x_c * A^T (compacted rows) ----------------
__global__ void __launch_bounds__(128,2) kproj_k(){
    int y = blockIdx.y;
    int b = y >> 4;
    int mBase = (y & 15)*TM;
    int cnt = g_cnt[b];
    int cntp = ((cnt + 127) >> 7) << 7;
    if (mBase >= cntp) return;
    extern __shared__ __align__(16) char dsm[];
    uint32_t sb = smem_u32(dsm);
    const __half** rowA = (const __half**)(dsm + NSTAGE*STAGE_H);
    const __half** rowB = rowA + TM;
    int t = threadIdx.x, L = t&31, w = t>>5;
    int wm = w&1, wn = w>>1;
    int nBase = blockIdx.x*TN;
    {
        int j = mBase + t; if (j >= cnt) j = cnt-1;
        rowA[t] = g_xh + ((size_t)b*SEQ + g_idx[b*SEQ + j])*DIM;
    }
    rowB[t] = g_A + (size_t)(nBase + t)*DIM;
    __syncthreads();
    uint32_t laneA = (L&15)*RSH + ((L>>4)&1)*16;
    uint32_t laneB = ((L&7) + ((L>>4)&1)*8)*RSH + ((L>>3)&1)*16;
    float acc[4][8][4] = {};
    gemm_main(sb, rowA, rowB, t, wm, wn, laneA, laneB, acc, KTH);
    int gq = L>>2, tig = L&3;
    __half* out = g_Kp + (size_t)b*SEQ*DIM;
#pragma unroll
    for (int mf=0;mf<4;mf++){
        int r0 = mBase + wm*64 + mf*16 + gq;
#pragma unroll
        for (int j=0;j<8;j++){
            int col = nBase + wn*64 + (j>>1)*16 + (j&1)*8 + tig*2;
            *(__half2*)&out[(size_t)r0*DIM + col]     = __floats2half2_rn(acc[mf][j][0], acc[mf][j][1]);
            *(__half2*)&out[(size_t)(r0+8)*DIM + col] = __floats2half2_rn(acc[mf][j][2], acc[mf][j][3]);
        }
    }
}

// ---------------- kernel 5: w[b][k] = v . x_c[k] (warp per k, coalesced) ----------------
__global__ void wcalc_k(){
    int b = blockIdx.y;
    int k = blockIdx.x*8 + (threadIdx.x >> 5);
    int lane = threadIdx.x & 31;
    int cnt = g_cnt[b];
    if (k >= cnt){ if (lane==0 && k < SEQ) g_w[b*SEQ + k] = 0.f; return; }
    const __half2* xr = (const __half2*)(g_xh + ((size_t)b*SEQ + g_idx[b*SEQ + k])*DIM);
    float s = 0.f;
#pragma unroll
    for (int i=0;i<12;i++){
        float2 f = __half22float2(xr[lane + 32*i]);
        int d = 2*(lane + 32*i);
        s += g_v[d]*f.x + g_v[d+1]*f.y;
    }
#pragma unroll
    for (int off=16; off; off>>=1) s += __shfl_xor_sync(0xffffffffu, s, off);
    if (lane==0) g_w[b*SEQ + k] = s;
}

// ---------------- kernel 6: scores = x*K'^T + w, P=exp, Z partials ----------------
__global__ void __launch_bounds__(128,2) scores_k(){
    int b = blockIdx.z;
    int cnt = g_cnt[b];
    int cntp = ((cnt + 127) >> 7) << 7;
    int nBase = blockIdx.x*TN;
    if (nBase >= cntp) return;
    int mBase = blockIdx.y*TM;
    extern __shared__ __align__(16) char dsm[];
    uint32_t sb = smem_u32(dsm);
    const __half** rowA = (const __half**)(dsm + NSTAGE*STAGE_H);
    const __half** rowB = rowA + TM;
    float* sW = (float*)(dsm + NSTAGE*STAGE_H + PTR_BYTES);
    float* sRow = (float*)dsm;                  // reused after mainloop
    int t = threadIdx.x, L = t&31, w = t>>5;
    int wm = w&1, wn = w>>1;
    rowA[t] = g_xh + ((size_t)b*SEQ + mBase + t)*DIM;
    {
        int j = nBase + t; if (j >= cnt) j = cnt-1;
        rowB[t] = g_Kp + ((size_t)b*SEQ + j)*DIM;
    }
    sW[t] = g_w[b*SEQ + nBase + t];
    __syncthreads();
    uint32_t laneA = (L&15)*RSH + ((L>>4)&1)*16;
    uint32_t laneB = ((L&7) + ((L>>4)&1)*8)*RSH + ((L>>3)&1)*16;
    float acc[4][8][4] = {};
    gemm_main(sb, rowA, rowB, t, wm, wn, laneA, laneB, acc, KTH);

    int gq = L>>2, tig = L&3;
    __nv_bfloat16* P = g_P + (size_t)b*SEQ*SEQ;
    float zl[4] = {0,0,0,0}, zh[4] = {0,0,0,0};
#pragma unroll
    for (int mf=0;mf<4;mf++){
        int q0 = mBase + wm*64 + mf*16 + gq;
#pragma unroll
        for (int j=0;j<8;j++){
            int coll = wn*64 + (j>>1)*16 + (j&1)*8 + tig*2;
            int kcol = nBase + coll;
            float w0 = sW[coll], w1 = sW[coll+1];
            float p0 = (kcol   < cnt) ? __expf(acc[mf][j][0]+w0) : 0.f;
            float p1 = (kcol+1 < cnt) ? __expf(acc[mf][j][1]+w1) : 0.f;
            float p2 = (kcol   < cnt) ? __expf(acc[mf][j][2]+w0) : 0.f;
            float p3 = (kcol+1 < cnt) ? __expf(acc[mf][j][3]+w1) : 0.f;
            *(__nv_bfloat162*)&P[(size_t)q0*SEQ + kcol]     = __floats2bfloat162_rn(p0,p1);
            *(__nv_bfloat162*)&P[(size_t)(q0+8)*SEQ + kcol] = __floats2bfloat162_rn(p2,p3);
            zl[mf] += p0+p1; zh[mf] += p2+p3;
        }
    }
    __syncthreads();
#pragma unroll
    for (int mf=0;mf<4;mf++){
        float x0 = zl[mf];
        x0 += __shfl_xor_sync(0xffffffffu, x0, 1);
        x0 += __shfl_xor_sync(0xffffffffu, x0, 2);
        float x1 = zh[mf];
        x1 += __shfl_xor_sync(0xffffffffu, x1, 1);
        x1 += __shfl_xor_sync(0xffffffffu, x1, 2);
        if (tig==0){
            sRow[(wm*64 + mf*16 + gq)*2     + wn] = x0;
            sRow[(wm*64 + mf*16 + gq + 8)*2 + wn] = x1;
        }
    }
    __syncthreads();
    if (t < TM){
        float z = sRow[t*2] + sRow[t*2+1];
        g_Zpart[((size_t)b*SEQ + mBase + t)*16 + blockIdx.x] = z;
    }
}

// ---------------- kernel 7: colsum with inline Z-reduce ----------------
__global__ void __launch_bounds__(256) colsum_k(){
    int b = blockIdx.y, qc = blockIdx.z;
    int cnt = g_cnt[b];
    int cntp = ((cnt + 127) >> 7) << 7;
    int t = threadIdx.x;
    int k0 = (blockIdx.x*256 + t)*2;
    float* dst = g_cpart + ((size_t)(b*QS + qc))*SEQ;
    if (blockIdx.x*512 >= cntp){ dst[k0] = 0.f; dst[k0+1] = 0.f; return; }
    __shared__ float sz[SEQ/QS];
    int qBase = qc*(SEQ/QS);
    {
        int nt = (cnt + 127) >> 7;
        float s = 0.f;
        const float* zp = &g_Zpart[((size_t)b*SEQ + qBase + t)*16];
        for (int j=0;j<nt;j++) s += zp[j];
        sz[t] = 1.0f/s;
    }
    __syncthreads();
    const uint32_t* P2 = (const uint32_t*)(g_P + (size_t)b*SEQ*SEQ + (size_t)qBase*SEQ)
                         + (blockIdx.x*256 + t);
    float c0=0.f, c1=0.f, d0=0.f, d1=0.f;
#pragma unroll 4
    for (int q=0; q<SEQ/QS; q+=2){
        uint32_t v0 = P2[(size_t)q*(SEQ/2)];
        uint32_t v1 = P2[(size_t)(q+1)*(SEQ/2)];
        c0 += bf16lo(v0)*sz[q];   c1 += bf16hi(v0)*sz[q];
        d0 += bf16lo(v1)*sz[q+1]; d1 += bf16hi(v1)*sz[q+1];
    }
    dst[k0] = c0+d0; dst[k0+1] = c1+d1;
}

// ---------------- kernel 8: ypart = c-chunk @ X_c ----------------
__global__ void __launch_bounds__(384) cx_k(){
    int b = blockIdx.y;
    int kc = blockIdx.x*64;
    int t = threadIdx.x;
    int cnt = g_cnt[b];
    float* yp = g_ypart + ((size_t)(b*XC + blockIdx.x))*DIM;
    if (kc >= cnt){ yp[2*t] = 0.f; yp[2*t+1] = 0.f; return; }
    __shared__ float sc[64];
    __shared__ int  sidx[64];
    if (t < 64){
        float s = 0.f;
#pragma unroll
        for (int qc=0;qc<QS;qc++)
            s += g_cpart[((size_t)(b*QS+qc))*SEQ + kc + t];
        sc[t] = (kc + t < cnt) ? s : 0.f;
        int j = kc + t; if (j >= cnt) j = cnt-1;
        sidx[t] = g_idx[b*SEQ + j];
    }
    __syncthreads();
    float a0=0.f, a1=0.f;
#pragma unroll 1
    for (int r=0;r<64;r+=4){
#pragma unroll
        for (int u=0;u<4;u++){
            float cv = sc[r+u];
            const __half2* xr = (const __half2*)(g_xh + ((size_t)b*SEQ + sidx[r+u])*DIM);
            float2 f = __half22float2(xr[t]);
            a0 += cv*f.x; a1 += cv*f.y;
        }
    }
    yp[2*t] = a0; yp[2*t+1] = a1;
}

// ---------------- kernel 9: out = (1/S)*y*Wv^T + bv ----------------
__global__ void __launch_bounds__(256) wv_k(const float* __restrict__ Wv,
        const float* __restrict__ bv, float* __restrict__ out){
    int b = blockIdx.y, t = threadIdx.x;
    __shared__ float sy[DIM];
    for (int d=t; d<DIM; d+=256){
        float s = 0.f;
#pragma unroll
        for (int ch=0; ch<XC; ch++) s += g_ypart[((size_t)(b*XC+ch))*DIM + d];
        sy[d] = s;
    }
    __syncthreads();
    int o = blockIdx.x*256 + t;
    const float* wr = Wv + (size_t)o*DIM;
    float acc = 0.f;
#pragma unroll 4
    for (int d=0; d<DIM; d+=4){
        float4 w4 = *(const float4*)(wr + d);
        acc += w4.x*sy[d] + w4.y*sy[d+1] + w4.z*sy[d+2] + w4.w*sy[d+3];
    }
    out[b*DIM + o] = acc * (1.0f/(float)SEQ) + bv[o];
}

// ---------------- launch ----------------
extern "C" void kernel_launch(void* const* d_in, const int* in_sizes, int n_in,
                              void* d_out, int out_size){
    const float* x    = (const float*)d_in[0];
    const int*   mask = (const int*)  d_in[1];
    const float* Wq   = (const float*)d_in[2];
    const float* bq   = (const float*)d_in[3];
    const float* Wk   = (const float*)d_in[4];
    const float* bk   = (const float*)d_in[5];
    const float* Wv   = (const float*)d_in[6];
    const float* bv   = (const float*)d_in[7];
    (void)bk;
    float* out = (float*)d_out;

    cudaFuncSetAttribute(gemmA_k,  cudaFuncAttributeMaxDynamicSharedMemorySize, SMEM_DYN);
    cudaFuncSetAttribute(kproj_k,  cudaFuncAttributeMaxDynamicSharedMemorySize, SMEM_DYN);
    cudaFuncSetAttribute(scores_k, cudaFuncAttributeMaxDynamicSharedMemorySize, SMEM_DYN);

    prep_all  <<<PREP_TOTAL, 256>>>(x, Wq, Wk, mask);
    gemmA_k   <<<dim3(6,6,4), 128, SMEM_DYN>>>();
    areduce_v <<<672, 256>>>(bq);
    kproj_k   <<<dim3(6,128), 128, SMEM_DYN>>>();
    wcalc_k   <<<dim3(256,NB), 256>>>();
    scores_k  <<<dim3(16,16,8), 128, SMEM_DYN>>>();
    colsum_k  <<<dim3(4,NB,QS), 256>>>();
    cx_k      <<<dim3(XC,NB), 384>>>();
    wv_k      <<<dim3(3,NB), 256>>>(Wv, bv, out);
}